// round 1
// baseline (speedup 1.0000x reference)
#include <cuda_runtime.h>
#include <math.h>

#define BB 4
#define NB 288
#define NC 32
#define NP 16
#define HW 196
#define HWC 49
#define EPSF 1e-5f

#define NVPHW (BB*NC*NP*HW)   // 401408
#define NCHW  (BB*NC*HW)      // 25088

// scratch (allocation-free: __device__ globals)
__device__ float    g_s[NVPHW];
__device__ float    g_v[NVPHW];
__device__ unsigned g_maxb[NCHW];
__device__ unsigned g_minb[NCHW];
__device__ float    g_inv[NCHW];
__device__ float    g_r[BB*NB*NC*HW];   // 7,225,344 floats

// ---------------------------------------------------------------------------
// init: zero s accumulator, set max/min identities (norms are > 0)
__global__ void k_init() {
    int i = blockIdx.x * blockDim.x + threadIdx.x;
    if (i < NCHW) { g_maxb[i] = 0u; g_minb[i] = 0x7F800000u; }
    if (i < NVPHW) g_s[i] = 0.0f;
}

// ---------------------------------------------------------------------------
// Pass A: per-(b,B,C,hw) pose norm -> atomic max/min over B; s0_raw = sum_B u
// block = (Bgroup of 16, C, b), 196 threads (one per hw)
__global__ void __launch_bounds__(196) k_passA(const float* __restrict__ u) {
    int bg = blockIdx.x;          // 0..17
    int c  = blockIdx.y;          // 0..31
    int b  = blockIdx.z;          // 0..3
    int hw = threadIdx.x;         // 0..195

    float sacc[NP];
#pragma unroll
    for (int p = 0; p < NP; p++) sacc[p] = 0.0f;

    int mmidx = (b * NC + c) * HW + hw;

    for (int bi = 0; bi < 16; bi++) {
        int Bidx = bg * 16 + bi;
        const float* up = u + ((size_t)((b * NB + Bidx) * NC + c) * NP) * HW + hw;
        float nacc = 0.0f;
#pragma unroll
        for (int p = 0; p < NP; p++) {
            float x = up[p * HW];
            sacc[p] += x;
            nacc += x * x;
        }
        unsigned nb = __float_as_uint(sqrtf(nacc + EPSF));
        atomicMax(&g_maxb[mmidx], nb);
        atomicMin(&g_minb[mmidx], nb);
    }

    int sbase = ((b * NC + c) * NP) * HW + hw;
#pragma unroll
    for (int p = 0; p < NP; p++) atomicAdd(&g_s[sbase + p * HW], sacc[p]);
}

// ---------------------------------------------------------------------------
// squash kernel: one thread per (b,C,hw)
// mode 0: compute inv, scale = inv/32, write g_v, zero g_s
// mode 1: scale = inv,   write g_v, zero g_s
// mode 2: scale = inv,   write v + a_out to output
__global__ void k_squash(float* __restrict__ vout, float* __restrict__ aout, int mode) {
    int i = blockIdx.x * blockDim.x + threadIdx.x;
    if (i >= NCHW) return;
    float inv;
    if (mode == 0) {
        float mx = __uint_as_float(g_maxb[i]);
        float mn = __uint_as_float(g_minb[i]);
        inv = 1.0f / (mx - mn);
        g_inv[i] = inv;
    } else {
        inv = g_inv[i];
    }
    float scale = (mode == 0) ? inv * (1.0f / 32.0f) : inv;

    int bc = i / HW, hw = i % HW;
    int sbase = bc * NP * HW + hw;

    float sv[NP];
    float n2 = EPSF;
#pragma unroll
    for (int p = 0; p < NP; p++) {
        float x = g_s[sbase + p * HW] * scale;
        sv[p] = x;
        n2 += x * x;
    }
    float f = 1.0f / (1.0f + sqrtf(n2));

    if (mode < 2) {
#pragma unroll
        for (int p = 0; p < NP; p++) {
            g_v[sbase + p * HW] = sv[p] * f;
            g_s[sbase + p * HW] = 0.0f;
        }
    } else {
        float av2 = EPSF;
#pragma unroll
        for (int p = 0; p < NP; p++) {
            float vv = sv[p] * f;
            vout[sbase + p * HW] = vv;
            av2 += vv * vv;
        }
        aout[i] = sqrtf(av2);
    }
}

// ---------------------------------------------------------------------------
// Routing pass (B and C):
//   block = (Bgroup of 32, hw-quarter, b), 392 threads: csub=tid/49 (0..7), hwq=tid%49
//   each thread owns 4 C values x 16 P x 1 hw
// shared: v_sh[25088], s_sh[25088], r_sh[1568], c_sh[1568], inv_sh[1568]
#define CPT 4
#define TBC 392

extern __shared__ float sh[];

__global__ void __launch_bounds__(TBC) k_route(const float* __restrict__ u, int first) {
    float* v_sh   = sh;
    float* s_sh   = sh + NC * NP * HWC;             // +25088
    float* r_sh   = sh + 2 * NC * NP * HWC;         // +50176
    float* c_sh   = r_sh + NC * HWC;                // +1568
    float* inv_sh = c_sh + NC * HWC;                // +1568

    int bg  = blockIdx.x;   // 0..8
    int hq  = blockIdx.y;   // 0..3
    int b   = blockIdx.z;   // 0..3
    int tid = threadIdx.x;
    int csub = tid / HWC;   // 0..7
    int hwq  = tid % HWC;   // 0..48
    int hw0  = hq * HWC;

    // load v slice + inv slice, zero s accumulator
    for (int e = tid; e < NC * NP * HWC; e += TBC) {
        int cp = e / HWC, q = e % HWC;
        v_sh[e] = g_v[(b * NC * NP + cp) * HW + hw0 + q];
        s_sh[e] = 0.0f;
    }
    for (int e = tid; e < NC * HWC; e += TBC) {
        int c = e / HWC, q = e % HWC;
        inv_sh[e] = g_inv[(b * NC + c) * HW + hw0 + q];
    }
    __syncthreads();

    for (int bi = 0; bi < 32; bi++) {
        int Bidx = bg * 32 + bi;
        size_t ubase = ((size_t)(b * NB + Bidx) * NC) * NP * HW + hw0 + hwq;

        // phase 1: r[c][hw] = inv * sum_P u * v   (+ stored r for second pass)
#pragma unroll
        for (int cc = 0; cc < CPT; cc++) {
            int c = csub * CPT + cc;
            float acc = 0.0f;
#pragma unroll
            for (int p = 0; p < NP; p++) {
                float x = u[ubase + (size_t)(c * NP + p) * HW];
                acc += x * v_sh[(c * NP + p) * HWC + hwq];
            }
            float rv = acc * inv_sh[c * HWC + hwq];
            int ridx = ((b * NB + Bidx) * NC + c) * HW + hw0 + hwq;
            if (first) g_r[ridx] = rv;
            else       rv += g_r[ridx];
            r_sh[c * HWC + hwq] = rv;
        }
        __syncthreads();

        // softmax over C (redundant per csub group; identical inputs)
        float m = -1e30f;
#pragma unroll
        for (int c = 0; c < NC; c++) m = fmaxf(m, r_sh[c * HWC + hwq]);
#pragma unroll
        for (int cc = 0; cc < CPT; cc++) {
            int c = csub * CPT + cc;
            c_sh[c * HWC + hwq] = __expf(r_sh[c * HWC + hwq] - m);
        }
        __syncthreads();
        float ssum = 0.0f;
#pragma unroll
        for (int c = 0; c < NC; c++) ssum += c_sh[c * HWC + hwq];
        float rs = 1.0f / ssum;

        // phase 2: s += (softmax c) * u  (u re-read; L2 hit)
#pragma unroll
        for (int cc = 0; cc < CPT; cc++) {
            int c = csub * CPT + cc;
            float cv = c_sh[c * HWC + hwq] * rs;
#pragma unroll
            for (int p = 0; p < NP; p++) {
                float x = u[ubase + (size_t)(c * NP + p) * HW];
                s_sh[(c * NP + p) * HWC + hwq] += cv * x;
            }
        }
        // no trailing sync needed: s_sh is thread-private by ownership;
        // r_sh rewrite and c_sh rewrite are fenced by the two syncs above.
    }
    __syncthreads();

    // flush partial s to global accumulator
    for (int e = tid; e < NC * NP * HWC; e += TBC) {
        int cp = e / HWC, q = e % HWC;
        atomicAdd(&g_s[(b * NC * NP + cp) * HW + hw0 + q], s_sh[e]);
    }
}

// ---------------------------------------------------------------------------
extern "C" void kernel_launch(void* const* d_in, const int* in_sizes, int n_in,
                              void* d_out, int out_size) {
    const float* u = (const float*)d_in[0];   // (4,288,32,16,14,14)
    // d_in[1] = a : unused by this routing variant
    float* out  = (float*)d_out;
    float* vout = out;                        // (4,32,16,14,14) = 401408
    float* aout = out + NVPHW;                // (4,32,14,14)    = 25088

    static const size_t shbytes = (size_t)(2 * NC * NP * HWC + 3 * NC * HWC) * sizeof(float); // 219,520 B
    cudaFuncSetAttribute(k_route, cudaFuncAttributeMaxDynamicSharedMemorySize, (int)shbytes);

    k_init<<<(NVPHW + 255) / 256, 256>>>();
    k_passA<<<dim3(18, 32, 4), 196>>>(u);
    k_squash<<<(NCHW + 255) / 256, 256>>>(nullptr, nullptr, 0);   // v0, zero s
    k_route<<<dim3(9, 4, 4), TBC, shbytes>>>(u, 1);               // r1 + s1
    k_squash<<<(NCHW + 255) / 256, 256>>>(nullptr, nullptr, 1);   // v1, zero s
    k_route<<<dim3(9, 4, 4), TBC, shbytes>>>(u, 0);               // r2 + s2
    k_squash<<<(NCHW + 255) / 256, 256>>>(vout, aout, 2);         // v2, a_out
}